// round 17
// baseline (speedup 1.0000x reference)
#include <cuda_runtime.h>
#include <cuda_fp16.h>
#include <cuda_bf16.h>
#include <cstddef>

// ---------------- problem geometry (fixed by setup_inputs) ----------------
#define BB    2
#define CC    64
#define HH    256
#define WW    256
#define PP    16
#define STEP  14
#define NHP   19
#define NPAT  361
#define BN    722
#define LL    256
#define NHEAD 4
#define DHEAD 16
#define MLP   128
#define HWSZ  65536

#define QSCALE 0.36067376022224085f   // 0.25 * log2(e)

#define KSH  24                       // K fp16 row stride (halves)
#define VSH  272                      // V^T fp16 row stride (halves)
#define HSH  136                      // h fp16 row stride (halves) = 68 words
#define WSH  72                       // weight fp16 row stride (halves)

// ---------------- scratch (fp16 interchange everywhere) ----------
__device__ __half g_t [(size_t)BN*LL*CC];
__device__ __half g_o [(size_t)BN*LL*CC];
__device__ __half g_xs[(size_t)BB*HWSZ*CC];
__device__ __half g_h1[(size_t)BB*HWSZ*MLP];

__device__ int   d_cov_cnt[256];
__device__ int   d_cov_p[256][2];
__device__ int   d_cov_o[256][2];
__device__ float d_invdiv[256];

__global__ void k_init()
{
    int r = threadIdx.x;
    if (r < 256) {
        int cnt = 0;
        for (int ph = 0; ph < NHP; ph++) {
            int top = min(STEP*ph, HH-PP);
            if (r >= top && r < top + PP && cnt < 2) {
                d_cov_p[r][cnt] = ph;
                d_cov_o[r][cnt] = r - top;
                cnt++;
            }
        }
        d_cov_cnt[r] = cnt;
    }
    if (threadIdx.x == 0) {
        float div[256];
        for (int i = 0; i < 256; i++) div[i] = 1.f;
        for (int i = STEP; i < HH + STEP - PP; i += STEP) {
            int top = (i + PP > HH) ? (HH - PP) : i;
            for (int r2 = top; r2 < i + PP - STEP; ++r2) div[r2] *= 2.f;
        }
        for (int i = 0; i < 256; i++) d_invdiv[i] = 1.f / div[i];
    }
}

// ---------------- mma helpers ---------------------------------------------
__device__ __forceinline__ float ex2(float x) {
    float r; asm("ex2.approx.ftz.f32 %0, %1;" : "=f"(r) : "f"(x)); return r;
}
__device__ __forceinline__ unsigned packh2(float x, float y) {
    __half2 h = __floats2half2_rn(x, y);
    return *(unsigned*)&h;
}
__device__ __forceinline__ void mma_f16(float* d, const unsigned* a,
                                        unsigned b0, unsigned b1) {
    asm volatile("mma.sync.aligned.m16n8k16.row.col.f32.f16.f16.f32 "
        "{%0,%1,%2,%3},{%4,%5,%6,%7},{%8,%9},{%0,%1,%2,%3};"
        : "+f"(d[0]), "+f"(d[1]), "+f"(d[2]), "+f"(d[3])
        : "r"(a[0]), "r"(a[1]), "r"(a[2]), "r"(a[3]), "r"(b0), "r"(b1));
}
__device__ __forceinline__ float gelu(float x) {
    return 0.5f * x * (1.f + erff(x * 0.70710678118654752f));
}
// fp16 GEMM, warp = 16 rows x 64 cols, K=64: A-frags [4 kc][4], B = wm [j][WSH]
__device__ __forceinline__ void gemm64h(const unsigned aq[4][4],
                                        const __half* __restrict__ wm,
                                        int g, int t, float acc[8][4]) {
    #pragma unroll
    for (int nt = 0; nt < 8; nt++)
        #pragma unroll
        for (int i = 0; i < 4; i++) acc[nt][i] = 0.f;
    #pragma unroll
    for (int nt = 0; nt < 8; nt++)
        #pragma unroll
        for (int kc = 0; kc < 4; kc++) {
            const __half* wb = wm + (nt*8 + g)*WSH + kc*16;
            unsigned b0 = *(const unsigned*)&wb[2*t];
            unsigned b1 = *(const unsigned*)&wb[8 + 2*t];
            mma_f16(acc[nt], aq[kc], b0, b1);
        }
}

// ---------------- kA: gather + LN1 + QKV + attention + o@wo + t -----------
__global__ __launch_bounds__(512) void kA(const float* __restrict__ x,
                                          const float* __restrict__ g1,
                                          const float* __restrict__ b1,
                                          const float* __restrict__ wq,
                                          const float* __restrict__ wk,
                                          const float* __restrict__ wv,
                                          const float* __restrict__ wo)
{
    extern __shared__ float sm[];
    float*  ps    = sm;                               // 17408 words
    __half* wsh   = (__half*)(sm + 17408);            // 3*4608 halves = 6912 words
    __half* vsm_h = (__half*)(sm + 17408 + 6912);     // 8704 words
    __half* hsm_h = (__half*)ps;                      // h fp16 in place
    __half* ksm_h = (__half*)ps;                      // K fp16 after barrier A
    __half* woh   = wsh;                              // wo after barrier B

    int tid = threadIdx.x;
    int bn = blockIdx.x;
    int b  = bn / NPAT, n = bn % NPAT;
    int ph = n / NHP,   pw = n % NHP;
    int top  = min(STEP*ph, HH-PP);
    int left = min(STEP*pw, WW-PP);
    const float* xb = x + (size_t)b * CC * HWSZ;

    for (int idx = tid; idx < 3*64*64; idx += 512) {
        int mat = idx >> 12; int rem = idx & 4095;
        int c = rem >> 6, j = rem & 63;
        const float* w = (mat == 0) ? wq : (mat == 1) ? wk : wv;
        wsh[mat*4608 + j*WSH + c] = __float2half(w[rem]);
    }
    for (int idx = tid; idx < CC*LL; idx += 512) {
        int c = idx >> 8, l = idx & 255;
        int li = l >> 4, lj = l & 15;
        ps[l*68 + c] = xb[(size_t)c*HWSZ + (size_t)(top+li)*WW + (left+lj)];
    }
    __syncthreads();

    int lane = tid & 31, warp = tid >> 5;
    {
        float ga = g1[lane], gb = g1[lane+32], ba = b1[lane], bbv = b1[lane+32];
        for (int l = warp; l < LL; l += 16) {
            float v0 = ps[l*68 + lane], v1 = ps[l*68 + lane + 32];
            size_t tb = ((size_t)bn*LL + l) * CC;
            g_t[tb + lane]      = __float2half(v0);
            g_t[tb + lane + 32] = __float2half(v1);
            float s = v0 + v1, ss = v0*v0 + v1*v1;
            #pragma unroll
            for (int o = 16; o; o >>= 1) {
                s  += __shfl_xor_sync(0xffffffffu, s,  o);
                ss += __shfl_xor_sync(0xffffffffu, ss, o);
            }
            float mean = s * (1.f/64.f);
            float var  = ss * (1.f/64.f) - mean*mean;
            float rstd = rsqrtf(var + 1e-5f);
            hsm_h[l*HSH + lane]      = __float2half((v0 - mean) * rstd * ga + ba);
            hsm_h[l*HSH + lane + 32] = __float2half((v1 - mean) * rstd * gb + bbv);
        }
    }
    __syncthreads();

    int g = lane >> 2, t = lane & 3;
    unsigned aqh16[4][4];
    {
        int r0 = (warp*16 + g)*HSH;
        #pragma unroll
        for (int kc = 0; kc < 4; kc++) {
            int c0 = kc*16 + 2*t;
            aqh16[kc][0] = *(const unsigned*)&hsm_h[r0 + c0];
            aqh16[kc][1] = *(const unsigned*)&hsm_h[r0 + 8*HSH + c0];
            aqh16[kc][2] = *(const unsigned*)&hsm_h[r0 + c0 + 8];
            aqh16[kc][3] = *(const unsigned*)&hsm_h[r0 + 8*HSH + c0 + 8];
        }
    }
    __syncthreads();   // barrier A: ps free (becomes K fp16)

    {
        float acc[8][4];
        gemm64h(aqh16, wsh + 4608, g, t, acc);   // K -> fp16 [head][tok][KSH]
        #pragma unroll
        for (int nt = 0; nt < 8; nt++) {
            int tok = warp*16 + g;
            int hd  = nt >> 1;
            int d0  = (nt & 1)*8 + 2*t;
            __half* kp = ksm_h + hd*(LL*KSH) + tok*KSH + d0;
            *(__half2*)kp            = __floats2half2_rn(acc[nt][0], acc[nt][1]);
            *(__half2*)(kp + 8*KSH)  = __floats2half2_rn(acc[nt][2], acc[nt][3]);
        }
        gemm64h(aqh16, wsh + 2*4608, g, t, acc); // V -> fp16 V^T [d][tok]
        #pragma unroll
        for (int nt = 0; nt < 8; nt++) {
            int tok = warp*16 + g;
            int d0  = nt*8 + 2*t;
            __half* vp = vsm_h + d0*VSH;
            vp[tok]           = __float2half(acc[nt][0]);
            vp[VSH + tok]     = __float2half(acc[nt][1]);
            vp[tok + 8]       = __float2half(acc[nt][2]);
            vp[VSH + tok + 8] = __float2half(acc[nt][3]);
        }
    }
    float qacc[8][4];
    gemm64h(aqh16, wsh, g, t, qacc);             // Q (registers)
    __syncthreads();   // barrier B: K/V visible; wsh mat-0 writable

    for (int idx = tid; idx < 4096; idx += 512) {
        int c = idx >> 6, j = idx & 63;
        woh[j*WSH + c] = __float2half(wo[idx]);
    }

    float oall[4][2][4];
    #pragma unroll
    for (int head = 0; head < NHEAD; head++) {
        unsigned aqh[4];
        {
            int h2 = head*2;
            aqh[0] = packh2(qacc[h2  ][0]*QSCALE, qacc[h2  ][1]*QSCALE);
            aqh[1] = packh2(qacc[h2  ][2]*QSCALE, qacc[h2  ][3]*QSCALE);
            aqh[2] = packh2(qacc[h2+1][0]*QSCALE, qacc[h2+1][1]*QSCALE);
            aqh[3] = packh2(qacc[h2+1][2]*QSCALE, qacc[h2+1][3]*QSCALE);
        }
        const __half* kh = ksm_h + head*(LL*KSH);
        const __half* vh = vsm_h + head*16*VSH;
        float oh[2][4];
        #pragma unroll
        for (int nd = 0; nd < 2; nd++)
            #pragma unroll
            for (int i = 0; i < 4; i++) oh[nd][i] = 0.f;
        float mrow[2] = {-1e30f, -1e30f};
        float drow[2] = {0.f, 0.f};

        #pragma unroll 1
        for (int jt = 0; jt < 8; jt++) {
            float s[4][4];
            #pragma unroll
            for (int nt = 0; nt < 4; nt++)
                #pragma unroll
                for (int i = 0; i < 4; i++) s[nt][i] = 0.f;
            #pragma unroll
            for (int nt = 0; nt < 4; nt++) {
                const __half* kb = kh + (jt*32 + nt*8 + g)*KSH;
                unsigned b0 = *(const unsigned*)&kb[2*t];
                unsigned b1 = *(const unsigned*)&kb[8 + 2*t];
                mma_f16(s[nt], aqh, b0, b1);
            }
            #pragma unroll
            for (int h = 0; h < 2; h++) {
                float mx = fmaxf(s[0][h*2], s[0][h*2+1]);
                #pragma unroll
                for (int nt = 1; nt < 4; nt++)
                    mx = fmaxf(mx, fmaxf(s[nt][h*2], s[nt][h*2+1]));
                mx = fmaxf(mx, __shfl_xor_sync(0xffffffffu, mx, 1));
                mx = fmaxf(mx, __shfl_xor_sync(0xffffffffu, mx, 2));
                float mn = fmaxf(mrow[h], mx);
                float scale = ex2(mrow[h] - mn);
                mrow[h] = mn;
                drow[h] *= scale;
                #pragma unroll
                for (int nd = 0; nd < 2; nd++) {
                    oh[nd][h*2]   *= scale;
                    oh[nd][h*2+1] *= scale;
                }
                float psum = 0.f;
                #pragma unroll
                for (int nt = 0; nt < 4; nt++) {
                    float e0 = ex2(s[nt][h*2]   - mn);
                    float e1 = ex2(s[nt][h*2+1] - mn);
                    s[nt][h*2] = e0; s[nt][h*2+1] = e1;
                    psum += e0 + e1;
                }
                drow[h] += psum;
            }
            unsigned pa[2][4];
            #pragma unroll
            for (int kc = 0; kc < 2; kc++) {
                pa[kc][0] = packh2(s[2*kc  ][0], s[2*kc  ][1]);
                pa[kc][1] = packh2(s[2*kc  ][2], s[2*kc  ][3]);
                pa[kc][2] = packh2(s[2*kc+1][0], s[2*kc+1][1]);
                pa[kc][3] = packh2(s[2*kc+1][2], s[2*kc+1][3]);
            }
            #pragma unroll
            for (int nd = 0; nd < 2; nd++) {
                #pragma unroll
                for (int kc = 0; kc < 2; kc++) {
                    const __half* vb = vh + (nd*8 + g)*VSH + jt*32 + kc*16;
                    unsigned b0 = *(const unsigned*)&vb[2*t];
                    unsigned b1 = *(const unsigned*)&vb[2*t + 8];
                    mma_f16(oh[nd], pa[kc], b0, b1);
                }
            }
        }
        float inv[2];
        #pragma unroll
        for (int h = 0; h < 2; h++) {
            float d = drow[h];
            d += __shfl_xor_sync(0xffffffffu, d, 1);
            d += __shfl_xor_sync(0xffffffffu, d, 2);
            inv[h] = 1.f / d;
        }
        #pragma unroll
        for (int nd = 0; nd < 2; nd++) {
            oall[head][nd][0] = oh[nd][0]*inv[0];
            oall[head][nd][1] = oh[nd][1]*inv[0];
            oall[head][nd][2] = oh[nd][2]*inv[1];
            oall[head][nd][3] = oh[nd][3]*inv[1];
        }
    }
    __syncthreads();   // barrier C: wo fp16 visible

    {
        float acc[8][4];
        #pragma unroll
        for (int nt = 0; nt < 8; nt++)
            #pragma unroll
            for (int i = 0; i < 4; i++) acc[nt][i] = 0.f;
        #pragma unroll
        for (int kc = 0; kc < 4; kc++) {
            unsigned ao[4];
            ao[0] = packh2(oall[kc][0][0], oall[kc][0][1]);
            ao[1] = packh2(oall[kc][0][2], oall[kc][0][3]);
            ao[2] = packh2(oall[kc][1][0], oall[kc][1][1]);
            ao[3] = packh2(oall[kc][1][2], oall[kc][1][3]);
            #pragma unroll
            for (int nt = 0; nt < 8; nt++) {
                const __half* wb = woh + (nt*8 + g)*WSH + kc*16;
                unsigned b0 = *(const unsigned*)&wb[2*t];
                unsigned b1 = *(const unsigned*)&wb[8 + 2*t];
                mma_f16(acc[nt], ao, b0, b1);
            }
        }
        size_t row0 = (size_t)bn * LL;
        #pragma unroll
        for (int nt = 0; nt < 8; nt++) {
            int row = warp*16 + g, col = nt*8 + 2*t;
            size_t a0 = (row0 + row)*CC + col;
            size_t a1 = (row0 + row + 8)*CC + col;
            float2 t0 = __half22float2(*(const __half2*)&g_t[a0]);
            float2 t1 = __half22float2(*(const __half2*)&g_t[a1]);
            *(__half2*)&g_o[a0] = __floats2half2_rn(acc[nt][0] + t0.x, acc[nt][1] + t0.y);
            *(__half2*)&g_o[a1] = __floats2half2_rn(acc[nt][2] + t1.x, acc[nt][3] + t1.y);
        }
    }
}

// ---------------- K4: patch_reverse gather + LN2 + fc1 + GELU -------------
__global__ __launch_bounds__(256, 3) void k4(const float* __restrict__ g2,
                                             const float* __restrict__ b2,
                                             const float* __restrict__ fc1w,
                                             const float* __restrict__ fc1b)
{
    extern __shared__ float sm4[];
    float*  xsm = sm4;                        // 128*68 fp32 -> fp16 in place
    __half* fwh = (__half*)(sm4 + 128*68);    // 128 j x WSH = 9216 halves
    __half* hsm_h = (__half*)xsm;
    int tid = threadIdx.x;
    size_t pix0 = (size_t)blockIdx.x * 128;
    int b4    = (int)(pix0 >> 16);
    int rrow  = (int)((pix0 & 65535) >> 8);
    int cbase = (int)(pix0 & 255);            // 0 or 128

    {
        int hc = d_cov_cnt[rrow];
        float idr = d_invdiv[rrow];
        for (int idx = tid; idx < 2048; idx += 256) {
            int row = idx >> 4, c4 = (idx & 15) * 4;
            int wcol = cbase + row;
            float4 a4; a4.x = 0.f; a4.y = 0.f; a4.z = 0.f; a4.w = 0.f;
            int wc2 = d_cov_cnt[wcol];
            for (int i = 0; i < hc; i++) {
                int n0 = d_cov_p[rrow][i]*NHP, l0 = d_cov_o[rrow][i]*PP;
                for (int k = 0; k < wc2; k++) {
                    int n = n0 + d_cov_p[wcol][k];
                    int l = l0 + d_cov_o[wcol][k];
                    uint2 v = *(const uint2*)&g_o[(((size_t)(b4*NPAT + n))*LL + l)*CC + c4];
                    float2 f0 = __half22float2(*(__half2*)&v.x);
                    float2 f1 = __half22float2(*(__half2*)&v.y);
                    a4.x += f0.x; a4.y += f0.y; a4.z += f1.x; a4.w += f1.y;
                }
            }
            float sc = idr * d_invdiv[wcol];
            a4.x *= sc; a4.y *= sc; a4.z *= sc; a4.w *= sc;
            *(float4*)&xsm[row*68 + c4] = a4;
            uint2 o2;
            *(__half2*)&o2.x = __floats2half2_rn(a4.x, a4.y);
            *(__half2*)&o2.y = __floats2half2_rn(a4.z, a4.w);
            *(uint2*)&g_xs[(pix0 + row)*CC + c4] = o2;
        }
    }
    for (int idx = tid; idx < 8192; idx += 256) {
        int c = idx >> 7, j = idx & 127;
        fwh[j*WSH + c] = __float2half(fc1w[idx]);
    }
    __syncthreads();

    int lane = tid & 31, warp = tid >> 5;
    float ga = g2[lane], gb = g2[lane+32], ba = b2[lane], bbv = b2[lane+32];
    for (int r = warp; r < 128; r += 8) {
        float v0 = xsm[r*68+lane], v1 = xsm[r*68+lane+32];
        float s = v0+v1, ss = v0*v0+v1*v1;
        #pragma unroll
        for (int o = 16; o; o >>= 1) {
            s  += __shfl_xor_sync(0xffffffffu, s,  o);
            ss += __shfl_xor_sync(0xffffffffu, ss, o);
        }
        float mean = s * (1.f/64.f);
        float var  = ss * (1.f/64.f) - mean*mean;
        float rstd = rsqrtf(var + 1e-5f);
        hsm_h[r*HSH + lane]      = __float2half((v0 - mean) * rstd * ga + ba);
        hsm_h[r*HSH + lane + 32] = __float2half((v1 - mean) * rstd * gb + bbv);
    }
    __syncthreads();

    int g = lane >> 2, t = lane & 3;
    int r0 = (warp*16 + g)*HSH;
    unsigned aq[4][4];
    #pragma unroll
    for (int kc = 0; kc < 4; kc++) {
        int c0 = kc*16 + 2*t;
        aq[kc][0] = *(const unsigned*)&hsm_h[r0 + c0];
        aq[kc][1] = *(const unsigned*)&hsm_h[r0 + 8*HSH + c0];
        aq[kc][2] = *(const unsigned*)&hsm_h[r0 + c0 + 8];
        aq[kc][3] = *(const unsigned*)&hsm_h[r0 + 8*HSH + c0 + 8];
    }
    #pragma unroll 1
    for (int pass = 0; pass < 2; pass++) {
        float acc[8][4];
        #pragma unroll
        for (int nt = 0; nt < 8; nt++) {
            float2 bb = *(const float2*)&fc1b[pass*64 + nt*8 + 2*t];
            acc[nt][0] = bb.x; acc[nt][1] = bb.y; acc[nt][2] = bb.x; acc[nt][3] = bb.y;
        }
        #pragma unroll
        for (int nt = 0; nt < 8; nt++)
            #pragma unroll
            for (int kc = 0; kc < 4; kc++) {
                const __half* wb = fwh + (pass*64 + nt*8 + g)*WSH + kc*16;
                unsigned b0 = *(const unsigned*)&wb[2*t];
                unsigned b1 = *(const unsigned*)&wb[8 + 2*t];
                mma_f16(acc[nt], aq[kc], b0, b1);
            }
        #pragma unroll
        for (int nt = 0; nt < 8; nt++) {
            int row = warp*16 + g, col = pass*64 + nt*8 + 2*t;
            __half2 h0 = __floats2half2_rn(gelu(acc[nt][0]), gelu(acc[nt][1]));
            __half2 h1 = __floats2half2_rn(gelu(acc[nt][2]), gelu(acc[nt][3]));
            *(__half2*)&g_h1[(pix0 + row)*MLP + col]     = h0;
            *(__half2*)&g_h1[(pix0 + row + 8)*MLP + col] = h1;
        }
    }
}

// ---------------- kB: dwconv 5x5 (half2 SIMD) + GELU + res + fc2 + store --
#define KB_SI_BYTES   36864
#define KB_FSM_BYTES  17408
#define KB_FW_BYTES   17408
#define KB_SMEM (KB_SI_BYTES + KB_FSM_BYTES + KB_FW_BYTES)
__global__ __launch_bounds__(256, 3) void kB(const float* __restrict__ dww,
                                             const float* __restrict__ dwb,
                                             const float* __restrict__ fc2w,
                                             const float* __restrict__ fc2b,
                                             float* __restrict__ out)
{
    extern __shared__ char smB[];
    __half* si  = (__half*)smB;
    __half* fsm = (__half*)(smB + KB_SI_BYTES);
    __half* fwh = (__half*)(smB + KB_SI_BYTES + KB_FSM_BYTES);
    float*  tile = (float*)smB;              // overlay si (dead after conv)

    int tid = threadIdx.x;
    int bx = blockIdx.x;
    int b  = bx >> 10;
    int tr = (bx >> 5) & 31, tc = bx & 31;
    int r0 = tr*8, c0 = tc*8;

    const uint4* h1v = (const uint4*)(g_h1 + (size_t)b * HWSZ * MLP);
    for (int idx = tid; idx < 144*16; idx += 256) {
        int p = idx >> 4, u = idx & 15;
        int hr = p / 12, hc = p % 12;
        int gr = r0 + hr - 2, gc = c0 + hc - 2;
        uint4 v = {0u, 0u, 0u, 0u};
        if (gr >= 0 && gr < 256 && gc >= 0 && gc < 256)
            v = h1v[(size_t)(gr*256 + gc)*16 + u];
        *(uint4*)&si[p*128 + u*8] = v;
    }
    for (int idx = tid; idx < 8192; idx += 256) {
        int c = idx >> 6, j = idx & 63;
        fwh[j*136 + c] = __float2half(fc2w[idx]);
    }
    __syncthreads();

    // conv: half2 SIMD — thread = (channel pair, 2 rows)
    {
        int c2 = (tid & 63) * 2;             // channel pair base
        int q  = tid >> 6;                   // 0..3 -> rows 2q, 2q+1
        __half2 w2[25];
        #pragma unroll
        for (int i = 0; i < 25; i++)
            w2[i] = __floats2half2_rn(dww[c2*25 + i], dww[(c2+1)*25 + i]);
        __half2 bias2 = __floats2half2_rn(dwb[c2], dwb[c2+1]);
        for (int r = q*2; r < q*2 + 2; r++) {
            __half2 acc8[8], cent[8];
            #pragma unroll
            for (int k = 0; k < 8; k++) acc8[k] = bias2;
            #pragma unroll
            for (int dy = 0; dy < 5; dy++) {
                __half2 v[12];
                int rowbase = ((r + dy)*12)*128 + c2;
                #pragma unroll
                for (int xx = 0; xx < 12; xx++)
                    v[xx] = *(const __half2*)&si[rowbase + xx*128];
                #pragma unroll
                for (int k = 0; k < 8; k++)
                    #pragma unroll
                    for (int dx = 0; dx < 5; dx++)
                        acc8[k] = __hfma2(v[k + dx], w2[dy*5 + dx], acc8[k]);
                if (dy == 2) {
                    #pragma unroll
                    for (int k = 0; k < 8; k++) cent[k] = v[k + 2];
                }
            }
            #pragma unroll
            for (int k = 0; k < 8; k++) {
                float2 af = __half22float2(acc8[k]);
                float2 cf = __half22float2(cent[k]);
                *(__half2*)&fsm[(r*8 + k)*136 + c2] =
                    __floats2half2_rn(cf.x + gelu(af.x), cf.y + gelu(af.y));
            }
        }
    }
    __syncthreads();

    int lane = tid & 31, w = tid >> 5, g = lane >> 2, t = lane & 3;
    {
        int mt = w >> 1, nh = w & 1;
        int rb = (mt*16 + g)*136;
        float acc[4][4];
        #pragma unroll
        for (int nt = 0; nt < 4; nt++)
            #pragma unroll
            for (int i = 0; i < 4; i++) acc[nt][i] = 0.f;
        #pragma unroll
        for (int kc = 0; kc < 8; kc++) {
            unsigned a[4];
            a[0] = *(const unsigned*)&fsm[rb + kc*16 + 2*t];
            a[1] = *(const unsigned*)&fsm[rb + 8*136 + kc*16 + 2*t];
            a[2] = *(const unsigned*)&fsm[rb + kc*16 + 8 + 2*t];
            a[3] = *(const unsigned*)&fsm[rb + 8*136 + kc*16 + 8 + 2*t];
            #pragma unroll
            for (int nt = 0; nt < 4; nt++) {
                const __half* wb = fwh + (nh*32 + nt*8 + g)*136 + kc*16;
                unsigned b0 = *(const unsigned*)&wb[2*t];
                unsigned b1 = *(const unsigned*)&wb[8 + 2*t];
                mma_f16(acc[nt], a, b0, b1);
            }
        }
        __syncthreads();   // fsm consumed; si overlay becomes out tile
        int p0 = mt*16 + g, p1 = p0 + 8;
        int rr0 = p0 >> 3, kk0 = p0 & 7;
        int rr1 = p1 >> 3, kk1 = p1 & 7;
        size_t base = (size_t)b*HWSZ;
        #pragma unroll
        for (int nt = 0; nt < 4; nt++) {
            int col = nh*32 + nt*8 + 2*t;
            float2 bb = *(const float2*)&fc2b[col];
            float2 x0 = __half22float2(*(const __half2*)
                &g_xs[(base + (size_t)(r0+rr0)*256 + c0 + kk0)*CC + col]);
            float2 x1 = __half22float2(*(const __half2*)
                &g_xs[(base + (size_t)(r0+rr1)*256 + c0 + kk1)*CC + col]);
            tile[(col  )*68 + p0] = acc[nt][0] + bb.x + x0.x;
            tile[(col+1)*68 + p0] = acc[nt][1] + bb.y + x0.y;
            tile[(col  )*68 + p1] = acc[nt][2] + bb.x + x1.x;
            tile[(col+1)*68 + p1] = acc[nt][3] + bb.y + x1.y;
        }
    }
    __syncthreads();

    for (int idx = tid; idx < 2048; idx += 256) {
        int c = idx >> 5, pp = idx & 31;
        int r = pp >> 2, k2 = (pp & 3) * 2;
        *(float2*)&out[((size_t)(b*CC + c))*HWSZ + (size_t)(r0 + r)*256 + c0 + k2] =
            *(const float2*)&tile[c*68 + r*8 + k2];
    }
}

// ---------------- launch ---------------------------------------------------
#define KA_SMEM ((17408 + 6912 + 8704) * 4)
#define K4_SMEM ((128*68 + 4608) * 4)

extern "C" void kernel_launch(void* const* d_in, const int* in_sizes, int n_in,
                              void* d_out, int out_size)
{
    const float* x    = (const float*)d_in[0];
    const float* ln1g = (const float*)d_in[1];
    const float* ln1b = (const float*)d_in[2];
    const float* wq   = (const float*)d_in[3];
    const float* wk   = (const float*)d_in[4];
    const float* wv   = (const float*)d_in[5];
    const float* wo   = (const float*)d_in[6];
    const float* ln2g = (const float*)d_in[7];
    const float* ln2b = (const float*)d_in[8];
    const float* fc1w = (const float*)d_in[9];
    const float* fc1b = (const float*)d_in[10];
    const float* dww  = (const float*)d_in[11];
    const float* dwb  = (const float*)d_in[12];
    const float* fc2w = (const float*)d_in[13];
    const float* fc2b = (const float*)d_in[14];
    float* out = (float*)d_out;

    static int s_attr = 0;
    if (!s_attr) {
        cudaFuncSetAttribute(kA, cudaFuncAttributeMaxDynamicSharedMemorySize, KA_SMEM);
        cudaFuncSetAttribute(k4, cudaFuncAttributeMaxDynamicSharedMemorySize, K4_SMEM);
        cudaFuncSetAttribute(kB, cudaFuncAttributeMaxDynamicSharedMemorySize, KB_SMEM);
        s_attr = 1;
    }

    k_init<<<1, 256>>>();
    kA<<<BN, 512, KA_SMEM>>>(x, ln1g, ln1b, wq, wk, wv, wo);
    k4<<<(BB*HWSZ)/128, 256, K4_SMEM>>>(ln2g, ln2b, fc1w, fc1b);
    kB<<<BB*1024, 256, KB_SMEM>>>(dww, dwb, fc2w, fc2b, out);
}